// round 2
// baseline (speedup 1.0000x reference)
#include <cuda_runtime.h>

// Scratch via __device__ globals (no allocations allowed).
#define MAX_BLOCKS 592
__device__ double g_partials[MAX_BLOCKS];
__device__ unsigned int g_retire_count = 0;  // reset to 0 by last block each run

// Single fused kernel: grid-stride float4 dot-product reduction, per-block
// partial into a dedicated slot, last retiring block reduces partials and
// writes the mean. Deterministic and graph-replayable (counter self-resets).
__global__ void __launch_bounds__(512)
bins_combiner_kernel(const float4* __restrict__ p4,
                     const float4* __restrict__ c4,
                     long long n4,
                     const float* __restrict__ p_tail,
                     const float* __restrict__ c_tail,
                     int n_tail,
                     float* __restrict__ out,
                     double inv_rows) {
    float acc = 0.0f;

    long long idx    = (long long)blockIdx.x * blockDim.x + threadIdx.x;
    long long stride = (long long)gridDim.x * blockDim.x;

    for (long long i = idx; i < n4; i += stride) {
        float4 a = p4[i];
        float4 b = c4[i];
        acc = fmaf(a.x, b.x, acc);
        acc = fmaf(a.y, b.y, acc);
        acc = fmaf(a.z, b.z, acc);
        acc = fmaf(a.w, b.w, acc);
    }

    // Scalar tail (first few threads of the grid).
    if (idx < n_tail) {
        acc = fmaf(p_tail[idx], c_tail[idx], acc);
    }

    // Warp reduction.
    #pragma unroll
    for (int off = 16; off > 0; off >>= 1)
        acc += __shfl_xor_sync(0xFFFFFFFFu, acc, off);

    // Block reduction via shared memory.
    __shared__ float warp_sums[16];  // 512 threads -> 16 warps
    __shared__ bool  is_last;
    int lane = threadIdx.x & 31;
    int wid  = threadIdx.x >> 5;
    if (lane == 0) warp_sums[wid] = acc;
    __syncthreads();

    if (wid == 0) {
        float v = (lane < 16) ? warp_sums[lane] : 0.0f;
        #pragma unroll
        for (int off = 16; off > 0; off >>= 1)
            v += __shfl_xor_sync(0xFFFFFFFFu, v, off);
        if (lane == 0) {
            g_partials[blockIdx.x] = (double)v;
            __threadfence();
            unsigned int prev = atomicAdd(&g_retire_count, 1u);
            is_last = (prev == gridDim.x - 1);
        }
    }
    __syncthreads();

    if (is_last) {
        __threadfence();  // acquire: make all partials visible
        // Parallel reduce of gridDim.x doubles across this block's 512 threads.
        double d = 0.0;
        for (unsigned int i = threadIdx.x; i < gridDim.x; i += blockDim.x)
            d += g_partials[i];
        #pragma unroll
        for (int off = 16; off > 0; off >>= 1)
            d += __shfl_xor_sync(0xFFFFFFFFu, d, off);

        __shared__ double dwarp[16];
        if (lane == 0) dwarp[wid] = d;
        __syncthreads();
        if (wid == 0) {
            double t = (lane < 16) ? dwarp[lane] : 0.0;
            #pragma unroll
            for (int off = 16; off > 0; off >>= 1)
                t += __shfl_xor_sync(0xFFFFFFFFu, t, off);
            if (lane == 0) {
                out[0] = (float)(t * inv_rows);
                __threadfence();
                g_retire_count = 0;  // reset for next graph replay
            }
        }
    }
}

extern "C" void kernel_launch(void* const* d_in, const int* in_sizes, int n_in,
                              void* d_out, int out_size) {
    const float* probs     = (const float*)d_in[0];
    const float* centroids = (const float*)d_in[1];
    float* out = (float*)d_out;

    long long n = (long long)in_sizes[0];   // N*K total elements
    const int K = 101;
    long long rows = n / K;

    long long n4 = n >> 2;                  // float4 count
    long long tail_start = n4 << 2;
    int n_tail = (int)(n - tail_start);

    // One full wave: 148 SMs x 4 blocks of 512 threads = 2048 thr/SM.
    int blocks = MAX_BLOCKS;  // 592
    bins_combiner_kernel<<<blocks, 512>>>(
        (const float4*)probs, (const float4*)centroids, n4,
        probs + tail_start, centroids + tail_start, n_tail,
        out, 1.0 / (double)rows);
}

// round 3
// speedup vs baseline: 1.0359x; 1.0359x over previous
#include <cuda_runtime.h>

// Scratch via __device__ globals (no allocations allowed).
#define NBLOCKS 1184   // 148 SMs x 8 blocks
__device__ double g_partials[NBLOCKS];
__device__ unsigned int g_retire_count = 0;  // reset to 0 by last block each run

// Single fused kernel: grid-stride float4 dot-product reduction, per-block
// partial into a dedicated slot, last retiring block reduces partials and
// writes the mean. min-blocks=4 forces <=32 regs so 4 CTAs/SM stay resident.
__global__ void __launch_bounds__(512, 4)
bins_combiner_kernel(const float4* __restrict__ p4,
                     const float4* __restrict__ c4,
                     long long n4,
                     const float* __restrict__ p_tail,
                     const float* __restrict__ c_tail,
                     int n_tail,
                     float* __restrict__ out,
                     double inv_rows) {
    float acc = 0.0f;

    long long idx    = (long long)blockIdx.x * blockDim.x + threadIdx.x;
    long long stride = (long long)gridDim.x * blockDim.x;

    for (long long i = idx; i < n4; i += stride) {
        float4 a = p4[i];
        float4 b = c4[i];
        acc = fmaf(a.x, b.x, acc);
        acc = fmaf(a.y, b.y, acc);
        acc = fmaf(a.z, b.z, acc);
        acc = fmaf(a.w, b.w, acc);
    }

    // Scalar tail (first few threads of the grid).
    if (idx < n_tail) {
        acc = fmaf(p_tail[idx], c_tail[idx], acc);
    }

    // Warp reduction.
    #pragma unroll
    for (int off = 16; off > 0; off >>= 1)
        acc += __shfl_xor_sync(0xFFFFFFFFu, acc, off);

    // Block reduction via shared memory.
    __shared__ float warp_sums[16];  // 512 threads -> 16 warps
    __shared__ bool  is_last;
    int lane = threadIdx.x & 31;
    int wid  = threadIdx.x >> 5;
    if (lane == 0) warp_sums[wid] = acc;
    __syncthreads();

    if (wid == 0) {
        float v = (lane < 16) ? warp_sums[lane] : 0.0f;
        #pragma unroll
        for (int off = 16; off > 0; off >>= 1)
            v += __shfl_xor_sync(0xFFFFFFFFu, v, off);
        if (lane == 0) {
            g_partials[blockIdx.x] = (double)v;
            __threadfence();
            unsigned int prev = atomicAdd(&g_retire_count, 1u);
            is_last = (prev == gridDim.x - 1);
        }
    }
    __syncthreads();

    if (is_last) {
        __threadfence();  // acquire: make all partials visible
        // Parallel reduce of gridDim.x doubles across this block's 512 threads.
        double d = 0.0;
        for (unsigned int i = threadIdx.x; i < gridDim.x; i += blockDim.x)
            d += g_partials[i];
        #pragma unroll
        for (int off = 16; off > 0; off >>= 1)
            d += __shfl_xor_sync(0xFFFFFFFFu, d, off);

        __shared__ double dwarp[16];
        if (lane == 0) dwarp[wid] = d;
        __syncthreads();
        if (wid == 0) {
            double t = (lane < 16) ? dwarp[lane] : 0.0;
            #pragma unroll
            for (int off = 16; off > 0; off >>= 1)
                t += __shfl_xor_sync(0xFFFFFFFFu, t, off);
            if (lane == 0) {
                out[0] = (float)(t * inv_rows);
                __threadfence();
                g_retire_count = 0;  // reset for next graph replay
            }
        }
    }
}

extern "C" void kernel_launch(void* const* d_in, const int* in_sizes, int n_in,
                              void* d_out, int out_size) {
    const float* probs     = (const float*)d_in[0];
    const float* centroids = (const float*)d_in[1];
    float* out = (float*)d_out;

    long long n = (long long)in_sizes[0];   // N*K total elements
    const int K = 101;
    long long rows = n / K;

    long long n4 = n >> 2;                  // float4 count
    long long tail_start = n4 << 2;
    int n_tail = (int)(n - tail_start);

    bins_combiner_kernel<<<NBLOCKS, 512>>>(
        (const float4*)probs, (const float4*)centroids, n4,
        probs + tail_start, centroids + tail_start, n_tail,
        out, 1.0 / (double)rows);
}

// round 5
// speedup vs baseline: 1.0536x; 1.0172x over previous
#include <cuda_runtime.h>

// Scratch via __device__ globals (no allocations allowed).
#define NBLOCKS 1184   // 148 SMs x 8 blocks
__device__ double g_partials[NBLOCKS];
__device__ unsigned int g_retire_count = 0;  // reset to 0 by last block each run

__device__ __forceinline__ float4 ldcs4(const float4* p) {
    return __ldcs(p);
}

// Single fused kernel: grid-stride, unroll-2 front-batched float4 streaming
// loads (4 independent LDG.128 per iteration), per-block partial into a
// dedicated slot, last retiring block reduces partials and writes the mean.
__global__ void __launch_bounds__(512)
bins_combiner_kernel(const float4* __restrict__ p4,
                     const float4* __restrict__ c4,
                     long long n4,
                     const float* __restrict__ p_tail,
                     const float* __restrict__ c_tail,
                     int n_tail,
                     float* __restrict__ out,
                     double inv_rows) {
    float acc0 = 0.0f, acc1 = 0.0f;

    long long idx     = (long long)blockIdx.x * blockDim.x + threadIdx.x;
    long long stride  = (long long)gridDim.x * blockDim.x;
    long long stride2 = stride << 1;

    long long i = idx;
    for (; i + stride < n4; i += stride2) {
        // Front-batch all 4 independent 16B loads, then consume.
        float4 a0 = ldcs4(p4 + i);
        float4 b0 = ldcs4(c4 + i);
        float4 a1 = ldcs4(p4 + i + stride);
        float4 b1 = ldcs4(c4 + i + stride);
        acc0 = fmaf(a0.x, b0.x, acc0);
        acc0 = fmaf(a0.y, b0.y, acc0);
        acc0 = fmaf(a0.z, b0.z, acc0);
        acc0 = fmaf(a0.w, b0.w, acc0);
        acc1 = fmaf(a1.x, b1.x, acc1);
        acc1 = fmaf(a1.y, b1.y, acc1);
        acc1 = fmaf(a1.z, b1.z, acc1);
        acc1 = fmaf(a1.w, b1.w, acc1);
    }
    if (i < n4) {
        float4 a0 = ldcs4(p4 + i);
        float4 b0 = ldcs4(c4 + i);
        acc0 = fmaf(a0.x, b0.x, acc0);
        acc0 = fmaf(a0.y, b0.y, acc0);
        acc0 = fmaf(a0.z, b0.z, acc0);
        acc0 = fmaf(a0.w, b0.w, acc0);
    }

    float acc = acc0 + acc1;

    // Scalar tail (first few threads of the grid).
    if (idx < n_tail) {
        acc = fmaf(p_tail[idx], c_tail[idx], acc);
    }

    // Warp reduction.
    #pragma unroll
    for (int off = 16; off > 0; off >>= 1)
        acc += __shfl_xor_sync(0xFFFFFFFFu, acc, off);

    // Block reduction via shared memory.
    __shared__ float warp_sums[16];  // 512 threads -> 16 warps
    __shared__ bool  is_last;
    int lane = threadIdx.x & 31;
    int wid  = threadIdx.x >> 5;
    if (lane == 0) warp_sums[wid] = acc;
    __syncthreads();

    if (wid == 0) {
        float v = (lane < 16) ? warp_sums[lane] : 0.0f;
        #pragma unroll
        for (int off = 16; off > 0; off >>= 1)
            v += __shfl_xor_sync(0xFFFFFFFFu, v, off);
        if (lane == 0) {
            g_partials[blockIdx.x] = (double)v;
            __threadfence();
            unsigned int prev = atomicAdd(&g_retire_count, 1u);
            is_last = (prev == gridDim.x - 1);
        }
    }
    __syncthreads();

    if (is_last) {
        __threadfence();  // acquire: make all partials visible
        double d = 0.0;
        for (unsigned int j = threadIdx.x; j < gridDim.x; j += blockDim.x)
            d += g_partials[j];
        #pragma unroll
        for (int off = 16; off > 0; off >>= 1)
            d += __shfl_xor_sync(0xFFFFFFFFu, d, off);

        __shared__ double dwarp[16];
        if (lane == 0) dwarp[wid] = d;
        __syncthreads();
        if (wid == 0) {
            double t = (lane < 16) ? dwarp[lane] : 0.0;
            #pragma unroll
            for (int off = 16; off > 0; off >>= 1)
                t += __shfl_xor_sync(0xFFFFFFFFu, t, off);
            if (lane == 0) {
                out[0] = (float)(t * inv_rows);
                __threadfence();
                g_retire_count = 0;  // reset for next graph replay
            }
        }
    }
}

extern "C" void kernel_launch(void* const* d_in, const int* in_sizes, int n_in,
                              void* d_out, int out_size) {
    const float* probs     = (const float*)d_in[0];
    const float* centroids = (const float*)d_in[1];
    float* out = (float*)d_out;

    long long n = (long long)in_sizes[0];   // N*K total elements
    const int K = 101;
    long long rows = n / K;

    long long n4 = n >> 2;                  // float4 count
    long long tail_start = n4 << 2;
    int n_tail = (int)(n - tail_start);

    bins_combiner_kernel<<<NBLOCKS, 512>>>(
        (const float4*)probs, (const float4*)centroids, n4,
        probs + tail_start, centroids + tail_start, n_tail,
        out, 1.0 / (double)rows);
}